// round 15
// baseline (speedup 1.0000x reference)
#include <cuda_runtime.h>
#include <cuda_bf16.h>
#include <cstdint>

// ---------------- problem constants ----------------
#define NPTS   512            // batch N
#define TT     300            // time steps
#define FF     150            // feature dim
#define HH     100            // hidden dim
#define G4     400            // 4*H gate rows
// x layout strides (floats): x[n][c][t][v][m], C=3,V=25,M=2
#define XSTR_N 45000
#define XSTR_C 15000
#define XSTR_T 50

// ---------------- scratch (device globals; no allocs allowed) ----------------
__device__ float g_Xp[(size_t)TT * NPTS * G4];       // encoder pre-activations (+bias)
__device__ float g_Hs[(size_t)(TT - 1) * NPTS * HH]; // decoder hidden states
__device__ float g_Wt[FF * G4];                      // enc_Wih transposed [f][g]
__device__ float g_Wd[G4 * HH];                      // folded decoder recurrent matrix
__device__ float g_biase[G4];
__device__ float g_bias0[G4];
__device__ float g_biasd[G4];

// ---------------- helpers ----------------
__device__ __forceinline__ void ffma2(float2& c, const float2& a, const float2& b) {
    asm("fma.rn.f32x2 %0, %1, %2, %0;"
        : "+l"(reinterpret_cast<unsigned long long&>(c))
        : "l"(reinterpret_cast<const unsigned long long&>(a)),
          "l"(reinterpret_cast<const unsigned long long&>(b)));
}

__device__ __forceinline__ float sigm(float x) {
    return __fdividef(1.0f, 1.0f + __expf(-x));
}
__device__ __forceinline__ float tanh_(float x) {
    return __fdividef(2.0f, 1.0f + __expf(-2.0f * x)) - 1.0f;
}

__device__ __forceinline__ void cpa16(void* dst_smem, const void* src) {
    uint32_t d = (uint32_t)__cvta_generic_to_shared(dst_smem);
    asm volatile("cp.async.ca.shared.global [%0], [%1], 16;" :: "r"(d), "l"(src) : "memory");
}
#define CPA_COMMIT() asm volatile("cp.async.commit_group;" ::: "memory")
#define CPA_WAIT0()  asm volatile("cp.async.wait_group 0;" ::: "memory")

// ---------------- prep 1: transpose enc_Wih, build biases ----------------
__global__ void prep_misc_kernel(const float* __restrict__ encWih,
                                 const float* __restrict__ encbih,
                                 const float* __restrict__ encbhh,
                                 const float* __restrict__ decWih,
                                 const float* __restrict__ decbih,
                                 const float* __restrict__ decbhh,
                                 const float* __restrict__ fcb) {
    const int gg  = blockIdx.x;   // gate row 0..399
    const int tid = threadIdx.x;  // 160 threads
    if (tid < FF) g_Wt[tid * G4 + gg] = encWih[gg * FF + tid];
    __shared__ float red[160];
    red[tid] = (tid < FF) ? decWih[gg * FF + tid] * fcb[tid] : 0.0f;
    __syncthreads();
    if (tid == 0) {
        float sum = 0.0f;
        for (int f = 0; f < FF; f++) sum += red[f];
        g_biase[gg] = encbih[gg] + encbhh[gg];
        float b0 = decbih[gg] + decbhh[gg];
        g_bias0[gg] = b0;
        g_biasd[gg] = b0 + sum;
    }
}

// ---------------- prep 2: Wd = dec_Whh + dec_Wih @ fc_W ----------------
__global__ void prep_wd_kernel(const float* __restrict__ decWih,
                               const float* __restrict__ decWhh,
                               const float* __restrict__ fcW) {
    const int gg = blockIdx.x;   // 0..399
    const int h  = threadIdx.x;  // 128 threads
    if (h < HH) {
        float acc = decWhh[gg * HH + h];
        for (int f = 0; f < FF; f++)
            acc += decWih[gg * FF + f] * fcW[f * HH + h];
        g_Wd[gg * HH + h] = acc;
    }
}

// ---------------- xproj: Xp[t*512+n][g] = xs[n,t,:] @ enc_Wih[g,:].T + biase[g] ----------------
// 40-row tiles, 512 threads, 2 CTAs/SM (smem 105.2 KB).
// A un-duplicated [150][42]; W double-buffered via cp.async; W loads float4
// (4 gates). Thread (gi=tid%25, ni=tid/25): rows ni*2..+1, gates 4gi+100j+{0..3}.
#define XP_NT    40
#define XP_AP    42            // A row pitch (floats)
#define XP_KC    25
#define XP_NCH   6
#define XP_CHF   (XP_KC * G4)  // floats per chunk = 10000
#define XP_SMEM  (150 * XP_AP * 4 + 2 * XP_CHF * 4)  // 25200 + 80000 = 105200 B

__global__ void __launch_bounds__(512, 2) xproj_kernel(const float* __restrict__ x) {
    extern __shared__ float sm[];
    float* As   = sm;                  // [150][XP_AP]
    float* Wbuf = sm + 150 * XP_AP;    // [2][XP_CHF]

    const int tid = threadIdx.x;
    const int nt0 = blockIdx.x * XP_NT;

    // stage A (x gather), un-duplicated
    for (int idx = tid; idx < XP_NT * FF; idx += 512) {
        int row = idx / FF, f = idx % FF;
        int nt = nt0 + row;
        int n = nt & 511, t = nt >> 9;
        As[f * XP_AP + row] =
            x[(size_t)n * XSTR_N + (f / 50) * XSTR_C + t * XSTR_T + (f % 50)];
    }
    // stage W chunk 0 via cp.async
    {
        float4* dst = reinterpret_cast<float4*>(Wbuf);
        const float4* src = reinterpret_cast<const float4*>(g_Wt);
        for (int i = tid; i < XP_CHF / 4; i += 512) cpa16(dst + i, src + i);
        CPA_COMMIT();
    }
    CPA_WAIT0();
    __syncthreads();

    const bool act = tid < 500;
    const int gi = tid % 25;   // gate base 4*gi + 100*j
    const int ni = tid / 25;   // rows ni*2, ni*2+1 (ni 0..19 active)

    float2 acc[2][8];
    #pragma unroll
    for (int r = 0; r < 2; r++)
        #pragma unroll
        for (int j = 0; j < 8; j++) acc[r][j] = make_float2(0.f, 0.f);

    for (int c = 0; c < XP_NCH; c++) {
        // issue async copy of chunk c+1 into the other buffer
        if (c + 1 < XP_NCH) {
            float4* dst = reinterpret_cast<float4*>(Wbuf + ((c + 1) & 1) * XP_CHF);
            const float4* src = reinterpret_cast<const float4*>(g_Wt + (c + 1) * XP_CHF);
            for (int i = tid; i < XP_CHF / 4; i += 512) cpa16(dst + i, src + i);
            CPA_COMMIT();
        }
        // compute on chunk c
        if (act) {
            const float* Wc = Wbuf + (c & 1) * XP_CHF;
            #pragma unroll
            for (int k = 0; k < XP_KC; k++) {
                float2 a2 = *reinterpret_cast<const float2*>(
                    &As[(c * XP_KC + k) * XP_AP + ni * 2]);
                float2 a0 = make_float2(a2.x, a2.x);
                float2 a1 = make_float2(a2.y, a2.y);
                #pragma unroll
                for (int j = 0; j < 4; j++) {
                    float4 w = *reinterpret_cast<const float4*>(
                        &Wc[k * G4 + 4 * gi + 100 * j]);
                    float2 w01 = make_float2(w.x, w.y);
                    float2 w23 = make_float2(w.z, w.w);
                    ffma2(acc[0][2 * j],     a0, w01);
                    ffma2(acc[0][2 * j + 1], a0, w23);
                    ffma2(acc[1][2 * j],     a1, w01);
                    ffma2(acc[1][2 * j + 1], a1, w23);
                }
            }
        }
        CPA_WAIT0();          // chunk c+1 landed
        __syncthreads();      // all threads done reading chunk c
    }

    if (act) {
        #pragma unroll
        for (int r = 0; r < 2; r++) {
            size_t base = (size_t)(nt0 + ni * 2 + r) * G4;
            #pragma unroll
            for (int j = 0; j < 4; j++) {
                int g0 = 4 * gi + 100 * j;
                float4 b4 = *reinterpret_cast<const float4*>(&g_biase[g0]);
                float4 o;
                o.x = acc[r][2 * j].x     + b4.x;
                o.y = acc[r][2 * j].y     + b4.y;
                o.z = acc[r][2 * j + 1].x + b4.z;
                o.w = acc[r][2 * j + 1].y + b4.w;
                *reinterpret_cast<float4*>(&g_Xp[base + g0]) = o;
            }
        }
    }
}

// ---------------- recurrence: warp-local cell, ONE barrier per step (R14 proven) ----------------
__global__ void __launch_bounds__(800, 1) recur_kernel(const float* __restrict__ encWhh,
                                                       const float* __restrict__ decWhh) {
    __shared__ __align__(16) float Hsm[2][4][104];   // double-buffered, pad [100..104) = 0
    __shared__ __align__(16) float Psm[25 * 160];    // [w][uj(40)][s(8)][type(2)][khalf]

    const int tid   = threadIdx.x;        // 0..799
    const int w     = tid >> 5;           // 0..24
    const int l     = tid & 31;
    const int uj    = l >> 3;             // 0..3
    const int type  = (l >> 1) & 3;       // 0=i 1=f 2=g 3=o
    const int khalf = l & 1;
    const int j     = w * 4 + uj;         // hidden unit 0..99
    const int gate  = type * 100 + j;
    const int b0    = khalf * 13;
    const int n0    = blockIdx.x * 4;

    const bool bact = l < 16;
    const int ujb = l >> 2;               // 0..3
    const int sb  = l & 3;                // 0..3
    const int jb  = w * 4 + ujb;

    const int pbase = w * 160 + uj * 40 + type * 2 + khalf;
    const int rbase = w * 160 + ujb * 40 + sb * 8;

    float4 W4[13];
    float creg = 0.0f;
    float pxi = 0.f, pxf = 0.f, pxg = 0.f, pxo = 0.f;

    reinterpret_cast<float*>(Hsm)[tid] = 0.0f;
    if (tid < 32) reinterpret_cast<float*>(Hsm)[800 + tid] = 0.0f;

    auto load_w = [&](const float* Wrow) {
        #pragma unroll
        for (int b = 0; b < 13; b++) {
            int k0 = (b0 + b) * 4;
            if (k0 < HH)
                W4[b] = *reinterpret_cast<const float4*>(Wrow + k0);
            else
                W4[b] = make_float4(0.f, 0.f, 0.f, 0.f);
        }
    };

    int p = 0;

    auto phaseA = [&]() {
        float2 acc[4];
        #pragma unroll
        for (int s = 0; s < 4; s++) acc[s] = make_float2(0.f, 0.f);
        #pragma unroll
        for (int b = 0; b < 13; b++) {
            float4 wv = W4[b];
            float2 wlo = make_float2(wv.x, wv.y);
            float2 whi = make_float2(wv.z, wv.w);
            const int off = (b0 + b) * 4;
            #pragma unroll
            for (int s = 0; s < 4; s++) {
                float4 h = *reinterpret_cast<const float4*>(&Hsm[p][s][off]);
                ffma2(acc[s], wlo, make_float2(h.x, h.y));
                ffma2(acc[s], whi, make_float2(h.z, h.w));
            }
        }
        #pragma unroll
        for (int s = 0; s < 4; s++)
            Psm[pbase + s * 8] = acc[s].x + acc[s].y;
    };

    auto phaseB = [&](float xi, float xf, float xg, float xo, bool store_h, int k) {
        float4 qa = *reinterpret_cast<const float4*>(&Psm[rbase]);
        float4 qb = *reinterpret_cast<const float4*>(&Psm[rbase + 4]);
        float i_ = sigm(qa.x + qa.y + xi);
        float f_ = sigm(qa.z + qa.w + xf);
        float g_ = tanh_(qb.x + qb.y + xg);
        float o_ = sigm(qb.z + qb.w + xo);
        creg = f_ * creg + i_ * g_;
        float hn = o_ * tanh_(creg);
        Hsm[p ^ 1][sb][jb] = hn;
        if (store_h)
            g_Hs[((size_t)k * NPTS + n0 + sb) * HH + jb] = hn;
    };

    load_w(encWhh + gate * HH);

    if (bact) {
        const float* pp = g_Xp + ((size_t)0 * NPTS + n0 + sb) * G4 + jb;
        pxi = pp[0]; pxf = pp[100]; pxg = pp[200]; pxo = pp[300];
    }
    __syncthreads();

    // ---- encoder: 300 steps ----
    for (int t = 0; t < TT; t++) {
        phaseA();
        __syncwarp();
        if (bact) {
            float xi = pxi, xf = pxf, xg = pxg, xo = pxo;
            if (t + 1 < TT) {
                const float* pp = g_Xp + ((size_t)(t + 1) * NPTS + n0 + sb) * G4 + jb;
                pxi = pp[0]; pxf = pp[100]; pxg = pp[200]; pxo = pp[300];
            }
            phaseB(xi, xf, xg, xo, false, 0);
        }
        __syncthreads();
        p ^= 1;
    }

    // ---- decoder step 0: raw dec_Whh (inp = 0) ----
    load_w(decWhh + gate * HH);
    if (bact) {
        pxi = g_bias0[jb];       pxf = g_bias0[100 + jb];
        pxg = g_bias0[200 + jb]; pxo = g_bias0[300 + jb];
    }
    phaseA();
    __syncwarp();
    if (bact) phaseB(pxi, pxf, pxg, pxo, true, 0);
    __syncthreads();
    p ^= 1;

    // ---- decoder steps 1..298: folded Wd ----
    load_w(g_Wd + gate * HH);
    if (bact) {
        pxi = g_biasd[jb];       pxf = g_biasd[100 + jb];
        pxg = g_biasd[200 + jb]; pxo = g_biasd[300 + jb];
    }
    for (int k = 1; k < TT - 1; k++) {
        phaseA();
        __syncwarp();
        if (bact) phaseB(pxi, pxf, pxg, pxo, true, k);
        __syncthreads();
        p ^= 1;
    }
}

// ---------------- zero out t=0 slice of the output ----------------
__global__ void zero_t0_kernel(float* __restrict__ out) {
    int idx = blockIdx.x * 256 + threadIdx.x;
    if (idx < NPTS * FF) {
        int n = idx / FF, f = idx % FF;
        out[(size_t)n * XSTR_N + (f / 50) * XSTR_C + (f % 50)] = 0.0f;
    }
}

// ---------------- fc (PROVEN: 32 rows, 320 threads, 2 CTAs/SM) ----------------
#define FC_ROWS 32
#define FC_WPAD 102
#define FC_SMEM ((FF * FC_WPAD + FC_ROWS * HH) * 4)  // 61200 + 12800 = 74000 B

__global__ void __launch_bounds__(320, 2) fc_kernel(const float* __restrict__ fcW,
                                                    const float* __restrict__ fcb,
                                                    float* __restrict__ out) {
    extern __shared__ float sm[];
    float* fcWs = sm;                 // [150][FC_WPAD]
    float* hs   = sm + FF * FC_WPAD;  // [32][100]

    const int tid = threadIdx.x;  // 320
    const int d0  = blockIdx.x * FC_ROWS;

    for (int idx = tid; idx < FF * HH; idx += 320) {
        int f = idx / HH, h = idx % HH;
        fcWs[f * FC_WPAD + h] = fcW[idx];
    }
    for (int idx = tid; idx < FC_ROWS * HH; idx += 320) {
        int r = idx / HH, h = idx % HH;
        hs[r * HH + h] = g_Hs[(size_t)(d0 + r) * HH + h];
    }
    __syncthreads();

    if (tid < 300) {
        const int rg = tid / 75;
        const int f  = 2 * (tid % 75);
        float2 acc[2][8];
        #pragma unroll
        for (int a = 0; a < 2; a++)
            #pragma unroll
            for (int r = 0; r < 8; r++) acc[a][r] = make_float2(0.f, 0.f);

        #pragma unroll
        for (int h2 = 0; h2 < 50; h2++) {
            float2 wa = *reinterpret_cast<const float2*>(&fcWs[f * FC_WPAD + 2 * h2]);
            float2 wb = *reinterpret_cast<const float2*>(&fcWs[(f + 1) * FC_WPAD + 2 * h2]);
            #pragma unroll
            for (int r = 0; r < 8; r++) {
                float2 hv = *reinterpret_cast<const float2*>(&hs[(rg * 8 + r) * HH + 2 * h2]);
                ffma2(acc[0][r], wa, hv);
                ffma2(acc[1][r], wb, hv);
            }
        }

        float b0 = fcb[f], b1 = fcb[f + 1];
        int c = f / 50, rr = f % 50;
        #pragma unroll
        for (int r = 0; r < 8; r++) {
            int d = d0 + rg * 8 + r;
            int n = d & 511;
            int t = (d >> 9) + 1;
            float2 o = make_float2(acc[0][r].x + acc[0][r].y + b0,
                                   acc[1][r].x + acc[1][r].y + b1);
            *reinterpret_cast<float2*>(&out[(size_t)n * XSTR_N + c * XSTR_C + t * XSTR_T + rr]) = o;
        }
    }
}

// ---------------- launch ----------------
extern "C" void kernel_launch(void* const* d_in, const int* in_sizes, int n_in,
                              void* d_out, int out_size) {
    const float* x       = (const float*)d_in[0];
    const float* encWih  = (const float*)d_in[1];
    const float* encWhh  = (const float*)d_in[2];
    const float* encbih  = (const float*)d_in[3];
    const float* encbhh  = (const float*)d_in[4];
    const float* decWih  = (const float*)d_in[5];
    const float* decWhh  = (const float*)d_in[6];
    const float* decbih  = (const float*)d_in[7];
    const float* decbhh  = (const float*)d_in[8];
    const float* fcW     = (const float*)d_in[9];
    const float* fcb     = (const float*)d_in[10];
    float* out = (float*)d_out;
    (void)in_sizes; (void)n_in; (void)out_size;

    cudaFuncSetAttribute(xproj_kernel, cudaFuncAttributeMaxDynamicSharedMemorySize, XP_SMEM);
    cudaFuncSetAttribute(fc_kernel,    cudaFuncAttributeMaxDynamicSharedMemorySize, FC_SMEM);

    prep_misc_kernel<<<G4, 160>>>(encWih, encbih, encbhh, decWih, decbih, decbhh, fcb);
    prep_wd_kernel<<<G4, 128>>>(decWih, decWhh, fcW);

    xproj_kernel<<<(TT * NPTS) / XP_NT, 512, XP_SMEM>>>(x);           // 3840 blocks, 2 CTAs/SM
    recur_kernel<<<NPTS / 4, 800>>>(encWhh, decWhh);                  // 128 blocks, 1 wave
    zero_t0_kernel<<<(NPTS * FF + 255) / 256, 256>>>(out);
    fc_kernel<<<((TT - 1) * NPTS) / FC_ROWS, 320, FC_SMEM>>>(fcW, fcb, out);  // 4784 blocks
}

// round 16
// speedup vs baseline: 1.1124x; 1.1124x over previous
#include <cuda_runtime.h>
#include <cuda_bf16.h>
#include <cstdint>

// ---------------- problem constants ----------------
#define NPTS   512            // batch N
#define TT     300            // time steps
#define FF     150            // feature dim
#define HH     100            // hidden dim
#define G4     400            // 4*H gate rows
// x layout strides (floats): x[n][c][t][v][m], C=3,V=25,M=2
#define XSTR_N 45000
#define XSTR_C 15000
#define XSTR_T 50

// ---------------- scratch (device globals; no allocs allowed) ----------------
__device__ float g_Xp[(size_t)TT * NPTS * G4];       // encoder pre-activations (+bias)
__device__ float g_Hs[(size_t)(TT - 1) * NPTS * HH]; // decoder hidden states
__device__ float g_Wt[FF * G4];                      // enc_Wih transposed [f][g]
__device__ float g_Wd[G4 * HH];                      // folded decoder recurrent matrix
__device__ float g_biase[G4];
__device__ float g_bias0[G4];
__device__ float g_biasd[G4];

// ---------------- helpers ----------------
__device__ __forceinline__ void ffma2(float2& c, const float2& a, const float2& b) {
    asm("fma.rn.f32x2 %0, %1, %2, %0;"
        : "+l"(reinterpret_cast<unsigned long long&>(c))
        : "l"(reinterpret_cast<const unsigned long long&>(a)),
          "l"(reinterpret_cast<const unsigned long long&>(b)));
}

__device__ __forceinline__ float sigm(float x) {
    return __fdividef(1.0f, 1.0f + __expf(-x));
}
__device__ __forceinline__ float tanh_(float x) {
    return __fdividef(2.0f, 1.0f + __expf(-2.0f * x)) - 1.0f;
}

// ---------------- prep 1: transpose enc_Wih, build biases ----------------
__global__ void prep_misc_kernel(const float* __restrict__ encWih,
                                 const float* __restrict__ encbih,
                                 const float* __restrict__ encbhh,
                                 const float* __restrict__ decWih,
                                 const float* __restrict__ decbih,
                                 const float* __restrict__ decbhh,
                                 const float* __restrict__ fcb) {
    const int gg  = blockIdx.x;   // gate row 0..399
    const int tid = threadIdx.x;  // 160 threads
    if (tid < FF) g_Wt[tid * G4 + gg] = encWih[gg * FF + tid];
    __shared__ float red[160];
    red[tid] = (tid < FF) ? decWih[gg * FF + tid] * fcb[tid] : 0.0f;
    __syncthreads();
    if (tid == 0) {
        float sum = 0.0f;
        for (int f = 0; f < FF; f++) sum += red[f];
        g_biase[gg] = encbih[gg] + encbhh[gg];
        float b0 = decbih[gg] + decbhh[gg];
        g_bias0[gg] = b0;
        g_biasd[gg] = b0 + sum;
    }
}

// ---------------- prep 2: Wd = dec_Whh + dec_Wih @ fc_W ----------------
__global__ void prep_wd_kernel(const float* __restrict__ decWih,
                               const float* __restrict__ decWhh,
                               const float* __restrict__ fcW) {
    const int gg = blockIdx.x;   // 0..399
    const int h  = threadIdx.x;  // 128 threads
    if (h < HH) {
        float acc = decWhh[gg * HH + h];
        for (int f = 0; f < FF; f++)
            acc += decWih[gg * FF + f] * fcW[f * HH + h];
        g_Wd[gg * HH + h] = acc;
    }
}

// ---------------- xproj (R14 structure + float4 W loads) ----------------
// 80-row tiles, 512 threads, double-buffered W chunks (register prefetch).
// Active 500: gi = tid%25, gates 4*gi + 100*j (j=0..3, float4 W loads);
// ni = tid/25, rows ni*4..ni*4+3.
#define XP_NT    80
#define XP_NTP   82            // even pad -> float4-aligned A loads
#define XP_KC    25
#define XP_NCH   6
#define XP_CHF   (XP_KC * G4)  // floats per chunk = 10000
#define XP_SMEM  (150 * XP_NTP * 8 + 2 * XP_CHF * 4)  // 98400 + 80000 = 178400 B

__global__ void __launch_bounds__(512, 1) xproj_kernel(const float* __restrict__ x) {
    extern __shared__ float sm[];
    float2* Adup = reinterpret_cast<float2*>(sm);        // [150][XP_NTP] (value duplicated)
    float*  Wbuf = sm + 150 * XP_NTP * 2;                // [2][XP_CHF]

    const int tid = threadIdx.x;
    const int nt0 = blockIdx.x * XP_NT;

    // stage A (x gather), duplicated into both f32x2 lanes
    for (int idx = tid; idx < XP_NT * FF; idx += 512) {
        int row = idx / FF, f = idx % FF;
        int nt = nt0 + row;
        int n = nt & 511, t = nt >> 9;
        float v = x[(size_t)n * XSTR_N + (f / 50) * XSTR_C + t * XSTR_T + (f % 50)];
        Adup[f * XP_NTP + row] = make_float2(v, v);
    }
    // stage W chunk 0
    {
        const float4* src = reinterpret_cast<const float4*>(g_Wt);
        float4* dst = reinterpret_cast<float4*>(Wbuf);
        #pragma unroll
        for (int i2 = 0; i2 < 5; i2++) {
            int idx = tid + i2 * 512;
            if (idx < XP_CHF / 4) dst[idx] = src[idx];
        }
    }
    __syncthreads();

    const bool act = tid < 500;
    const int gi = tid % 25;   // gate base 4*gi + 100*j
    const int ni = tid / 25;   // rows ni*4 .. ni*4+3  (ni 0..19 active)

    float2 acc[4][8];
    #pragma unroll
    for (int r = 0; r < 4; r++)
        #pragma unroll
        for (int j = 0; j < 8; j++) acc[r][j] = make_float2(0.f, 0.f);

    for (int c = 0; c < XP_NCH; c++) {
        // prefetch next chunk into registers (latency hidden under compute)
        float4 pf[5];
        const bool has = (c + 1 < XP_NCH);
        if (has) {
            const float4* src = reinterpret_cast<const float4*>(g_Wt + (c + 1) * XP_CHF);
            #pragma unroll
            for (int i2 = 0; i2 < 5; i2++) {
                int idx = tid + i2 * 512;
                pf[i2] = (idx < XP_CHF / 4) ? src[idx] : make_float4(0.f, 0.f, 0.f, 0.f);
            }
        }
        const float* Wc = Wbuf + (c & 1) * XP_CHF;
        if (act) {
            #pragma unroll
            for (int k = 0; k < XP_KC; k++) {
                const float4 a01 = *reinterpret_cast<const float4*>(
                    &Adup[(c * XP_KC + k) * XP_NTP + ni * 4]);
                const float4 a23 = *reinterpret_cast<const float4*>(
                    &Adup[(c * XP_KC + k) * XP_NTP + ni * 4 + 2]);
                float2 a0 = make_float2(a01.x, a01.y);
                float2 a1 = make_float2(a01.z, a01.w);
                float2 a2 = make_float2(a23.x, a23.y);
                float2 a3 = make_float2(a23.z, a23.w);
                #pragma unroll
                for (int j = 0; j < 4; j++) {
                    float4 w = *reinterpret_cast<const float4*>(
                        &Wc[k * G4 + 4 * gi + 100 * j]);
                    float2 w01 = make_float2(w.x, w.y);
                    float2 w23 = make_float2(w.z, w.w);
                    ffma2(acc[0][2 * j],     a0, w01);
                    ffma2(acc[0][2 * j + 1], a0, w23);
                    ffma2(acc[1][2 * j],     a1, w01);
                    ffma2(acc[1][2 * j + 1], a1, w23);
                    ffma2(acc[2][2 * j],     a2, w01);
                    ffma2(acc[2][2 * j + 1], a2, w23);
                    ffma2(acc[3][2 * j],     a3, w01);
                    ffma2(acc[3][2 * j + 1], a3, w23);
                }
            }
        }
        if (has) {
            float4* dst = reinterpret_cast<float4*>(Wbuf + ((c + 1) & 1) * XP_CHF);
            #pragma unroll
            for (int i2 = 0; i2 < 5; i2++) {
                int idx = tid + i2 * 512;
                if (idx < XP_CHF / 4) dst[idx] = pf[i2];
            }
        }
        __syncthreads();
    }

    if (act) {
        #pragma unroll
        for (int r = 0; r < 4; r++) {
            size_t base = (size_t)(nt0 + ni * 4 + r) * G4;
            #pragma unroll
            for (int j = 0; j < 4; j++) {
                int g0 = 4 * gi + 100 * j;
                float4 b4 = *reinterpret_cast<const float4*>(&g_biase[g0]);
                float4 o;
                o.x = acc[r][2 * j].x     + b4.x;
                o.y = acc[r][2 * j].y     + b4.y;
                o.z = acc[r][2 * j + 1].x + b4.z;
                o.w = acc[r][2 * j + 1].y + b4.w;
                *reinterpret_cast<float4*>(&g_Xp[base + g0]) = o;
            }
        }
    }
}

// ---------------- recurrence: warp-local cell, ONE barrier per step (R14 proven) ----------------
__global__ void __launch_bounds__(800, 1) recur_kernel(const float* __restrict__ encWhh,
                                                       const float* __restrict__ decWhh) {
    __shared__ __align__(16) float Hsm[2][4][104];   // double-buffered, pad [100..104) = 0
    __shared__ __align__(16) float Psm[25 * 160];    // [w][uj(40)][s(8)][type(2)][khalf]

    const int tid   = threadIdx.x;        // 0..799
    const int w     = tid >> 5;           // 0..24
    const int l     = tid & 31;
    const int uj    = l >> 3;             // 0..3
    const int type  = (l >> 1) & 3;       // 0=i 1=f 2=g 3=o
    const int khalf = l & 1;
    const int j     = w * 4 + uj;         // hidden unit 0..99
    const int gate  = type * 100 + j;
    const int b0    = khalf * 13;
    const int n0    = blockIdx.x * 4;

    const bool bact = l < 16;
    const int ujb = l >> 2;               // 0..3
    const int sb  = l & 3;                // 0..3
    const int jb  = w * 4 + ujb;

    const int pbase = w * 160 + uj * 40 + type * 2 + khalf;
    const int rbase = w * 160 + ujb * 40 + sb * 8;

    float4 W4[13];
    float creg = 0.0f;
    float pxi = 0.f, pxf = 0.f, pxg = 0.f, pxo = 0.f;

    reinterpret_cast<float*>(Hsm)[tid] = 0.0f;
    if (tid < 32) reinterpret_cast<float*>(Hsm)[800 + tid] = 0.0f;

    auto load_w = [&](const float* Wrow) {
        #pragma unroll
        for (int b = 0; b < 13; b++) {
            int k0 = (b0 + b) * 4;
            if (k0 < HH)
                W4[b] = *reinterpret_cast<const float4*>(Wrow + k0);
            else
                W4[b] = make_float4(0.f, 0.f, 0.f, 0.f);
        }
    };

    int p = 0;

    auto phaseA = [&]() {
        float2 acc[4];
        #pragma unroll
        for (int s = 0; s < 4; s++) acc[s] = make_float2(0.f, 0.f);
        #pragma unroll
        for (int b = 0; b < 13; b++) {
            float4 wv = W4[b];
            float2 wlo = make_float2(wv.x, wv.y);
            float2 whi = make_float2(wv.z, wv.w);
            const int off = (b0 + b) * 4;
            #pragma unroll
            for (int s = 0; s < 4; s++) {
                float4 h = *reinterpret_cast<const float4*>(&Hsm[p][s][off]);
                ffma2(acc[s], wlo, make_float2(h.x, h.y));
                ffma2(acc[s], whi, make_float2(h.z, h.w));
            }
        }
        #pragma unroll
        for (int s = 0; s < 4; s++)
            Psm[pbase + s * 8] = acc[s].x + acc[s].y;
    };

    auto phaseB = [&](float xi, float xf, float xg, float xo, bool store_h, int k) {
        float4 qa = *reinterpret_cast<const float4*>(&Psm[rbase]);
        float4 qb = *reinterpret_cast<const float4*>(&Psm[rbase + 4]);
        float i_ = sigm(qa.x + qa.y + xi);
        float f_ = sigm(qa.z + qa.w + xf);
        float g_ = tanh_(qb.x + qb.y + xg);
        float o_ = sigm(qb.z + qb.w + xo);
        creg = f_ * creg + i_ * g_;
        float hn = o_ * tanh_(creg);
        Hsm[p ^ 1][sb][jb] = hn;
        if (store_h)
            g_Hs[((size_t)k * NPTS + n0 + sb) * HH + jb] = hn;
    };

    load_w(encWhh + gate * HH);

    if (bact) {
        const float* pp = g_Xp + ((size_t)0 * NPTS + n0 + sb) * G4 + jb;
        pxi = pp[0]; pxf = pp[100]; pxg = pp[200]; pxo = pp[300];
    }
    __syncthreads();

    // ---- encoder: 300 steps ----
    for (int t = 0; t < TT; t++) {
        phaseA();
        __syncwarp();
        if (bact) {
            float xi = pxi, xf = pxf, xg = pxg, xo = pxo;
            if (t + 1 < TT) {
                const float* pp = g_Xp + ((size_t)(t + 1) * NPTS + n0 + sb) * G4 + jb;
                pxi = pp[0]; pxf = pp[100]; pxg = pp[200]; pxo = pp[300];
            }
            phaseB(xi, xf, xg, xo, false, 0);
        }
        __syncthreads();
        p ^= 1;
    }

    // ---- decoder step 0: raw dec_Whh (inp = 0) ----
    load_w(decWhh + gate * HH);
    if (bact) {
        pxi = g_bias0[jb];       pxf = g_bias0[100 + jb];
        pxg = g_bias0[200 + jb]; pxo = g_bias0[300 + jb];
    }
    phaseA();
    __syncwarp();
    if (bact) phaseB(pxi, pxf, pxg, pxo, true, 0);
    __syncthreads();
    p ^= 1;

    // ---- decoder steps 1..298: folded Wd ----
    load_w(g_Wd + gate * HH);
    if (bact) {
        pxi = g_biasd[jb];       pxf = g_biasd[100 + jb];
        pxg = g_biasd[200 + jb]; pxo = g_biasd[300 + jb];
    }
    for (int k = 1; k < TT - 1; k++) {
        phaseA();
        __syncwarp();
        if (bact) phaseB(pxi, pxf, pxg, pxo, true, k);
        __syncthreads();
        p ^= 1;
    }
}

// ---------------- zero out t=0 slice of the output ----------------
__global__ void zero_t0_kernel(float* __restrict__ out) {
    int idx = blockIdx.x * 256 + threadIdx.x;
    if (idx < NPTS * FF) {
        int n = idx / FF, f = idx % FF;
        out[(size_t)n * XSTR_N + (f / 50) * XSTR_C + (f % 50)] = 0.0f;
    }
}

// ---------------- fc (PROVEN: 32 rows, 320 threads, 2 CTAs/SM) ----------------
#define FC_ROWS 32
#define FC_WPAD 102
#define FC_SMEM ((FF * FC_WPAD + FC_ROWS * HH) * 4)  // 61200 + 12800 = 74000 B

__global__ void __launch_bounds__(320, 2) fc_kernel(const float* __restrict__ fcW,
                                                    const float* __restrict__ fcb,
                                                    float* __restrict__ out) {
    extern __shared__ float sm[];
    float* fcWs = sm;                 // [150][FC_WPAD]
    float* hs   = sm + FF * FC_WPAD;  // [32][100]

    const int tid = threadIdx.x;  // 320
    const int d0  = blockIdx.x * FC_ROWS;

    for (int idx = tid; idx < FF * HH; idx += 320) {
        int f = idx / HH, h = idx % HH;
        fcWs[f * FC_WPAD + h] = fcW[idx];
    }
    for (int idx = tid; idx < FC_ROWS * HH; idx += 320) {
        int r = idx / HH, h = idx % HH;
        hs[r * HH + h] = g_Hs[(size_t)(d0 + r) * HH + h];
    }
    __syncthreads();

    if (tid < 300) {
        const int rg = tid / 75;
        const int f  = 2 * (tid % 75);
        float2 acc[2][8];
        #pragma unroll
        for (int a = 0; a < 2; a++)
            #pragma unroll
            for (int r = 0; r < 8; r++) acc[a][r] = make_float2(0.f, 0.f);

        #pragma unroll
        for (int h2 = 0; h2 < 50; h2++) {
            float2 wa = *reinterpret_cast<const float2*>(&fcWs[f * FC_WPAD + 2 * h2]);
            float2 wb = *reinterpret_cast<const float2*>(&fcWs[(f + 1) * FC_WPAD + 2 * h2]);
            #pragma unroll
            for (int r = 0; r < 8; r++) {
                float2 hv = *reinterpret_cast<const float2*>(&hs[(rg * 8 + r) * HH + 2 * h2]);
                ffma2(acc[0][r], wa, hv);
                ffma2(acc[1][r], wb, hv);
            }
        }

        float b0 = fcb[f], b1 = fcb[f + 1];
        int c = f / 50, rr = f % 50;
        #pragma unroll
        for (int r = 0; r < 8; r++) {
            int d = d0 + rg * 8 + r;
            int n = d & 511;
            int t = (d >> 9) + 1;
            float2 o = make_float2(acc[0][r].x + acc[0][r].y + b0,
                                   acc[1][r].x + acc[1][r].y + b1);
            *reinterpret_cast<float2*>(&out[(size_t)n * XSTR_N + c * XSTR_C + t * XSTR_T + rr]) = o;
        }
    }
}

// ---------------- launch ----------------
extern "C" void kernel_launch(void* const* d_in, const int* in_sizes, int n_in,
                              void* d_out, int out_size) {
    const float* x       = (const float*)d_in[0];
    const float* encWih  = (const float*)d_in[1];
    const float* encWhh  = (const float*)d_in[2];
    const float* encbih  = (const float*)d_in[3];
    const float* encbhh  = (const float*)d_in[4];
    const float* decWih  = (const float*)d_in[5];
    const float* decWhh  = (const float*)d_in[6];
    const float* decbih  = (const float*)d_in[7];
    const float* decbhh  = (const float*)d_in[8];
    const float* fcW     = (const float*)d_in[9];
    const float* fcb     = (const float*)d_in[10];
    float* out = (float*)d_out;
    (void)in_sizes; (void)n_in; (void)out_size;

    cudaFuncSetAttribute(xproj_kernel, cudaFuncAttributeMaxDynamicSharedMemorySize, XP_SMEM);
    cudaFuncSetAttribute(fc_kernel,    cudaFuncAttributeMaxDynamicSharedMemorySize, FC_SMEM);

    prep_misc_kernel<<<G4, 160>>>(encWih, encbih, encbhh, decWih, decbih, decbhh, fcb);
    prep_wd_kernel<<<G4, 128>>>(decWih, decWhh, fcW);

    xproj_kernel<<<(TT * NPTS) / XP_NT, 512, XP_SMEM>>>(x);           // 1920 blocks
    recur_kernel<<<NPTS / 4, 800>>>(encWhh, decWhh);                  // 128 blocks, 1 wave
    zero_t0_kernel<<<(NPTS * FF + 255) / 256, 256>>>(out);
    fc_kernel<<<((TT - 1) * NPTS) / FC_ROWS, 320, FC_SMEM>>>(fcW, fcb, out);  // 4784 blocks
}